// round 11
// baseline (speedup 1.0000x reference)
#include <cuda_runtime.h>
#include <math.h>

#define B 64
#define S 512
#define H 512
#define E 512
#define NSEG 64
#define MR (B*S)
#define NPROJ 3072
#define POOL (B*NSEG*2*H)
#define NBLK 128

__device__ float g_X[(size_t)MR*E];
__device__ float g_XP[(size_t)MR*NPROJ];
__device__ float g_ctx[(size_t)MR*2*H];
__device__ float g_h[2][2][B][H];
__device__ unsigned long long g_bar;

__device__ __forceinline__ void gbar(){
  __syncthreads();
  if (threadIdx.x == 0){
    __threadfence();
    unsigned long long t = atomicAdd(&g_bar, 1ULL);
    unsigned long long target = (t/(unsigned long long)NBLK + 1ULL)*(unsigned long long)NBLK;
    while (*(volatile unsigned long long*)&g_bar < target) __nanosleep(32);
    __threadfence();
  }
  __syncthreads();
}

__global__ void k_embed(const int* __restrict__ seq, const float* __restrict__ emb){
  size_t i = (size_t)blockIdx.x*256 + threadIdx.x;   // MR*128 float4 slots
  int c = (int)(i & 127); size_t row = i >> 7;
  int tok = seq[row];
  reinterpret_cast<float4*>(g_X)[row*128 + c] =
      reinterpret_cast<const float4*>(emb)[(size_t)tok*128 + c];
}

__global__ void __launch_bounds__(256) k_gemm(
    const float* __restrict__ wf, const float* __restrict__ wb,
    const float* __restrict__ bf, const float* __restrict__ bb){
  __shared__ __align__(16) float sA[16][68];
  __shared__ __align__(16) float sB[16][68];
  int nb = blockIdx.x, mb = blockIdx.y;              // nb 0..47, mb 0..511
  const float* W; const float* bias; int nloc;
  if (nb < 24){ W = wf; bias = bf; nloc = nb*64; }
  else        { W = wb; bias = bb; nloc = (nb-24)*64; }
  int tid = threadIdx.x;
  int m0 = (tid & 15)*4, n0 = (tid >> 4)*4;
  int lr = tid >> 2, lc = tid & 3;
  float acc[4][4] = {};
  for (int kt = 0; kt < 32; kt++){
    float4 av = *(const float4*)&g_X[((size_t)(mb*64+lr))*E + kt*16 + lc*4];
    float4 bv = *(const float4*)&W  [((size_t)(nloc+lr))*E + kt*16 + lc*4];
    __syncthreads();
    sA[lc*4+0][lr]=av.x; sA[lc*4+1][lr]=av.y; sA[lc*4+2][lr]=av.z; sA[lc*4+3][lr]=av.w;
    sB[lc*4+0][lr]=bv.x; sB[lc*4+1][lr]=bv.y; sB[lc*4+2][lr]=bv.z; sB[lc*4+3][lr]=bv.w;
    __syncthreads();
    #pragma unroll
    for (int k = 0; k < 16; k++){
      float4 a4 = *(const float4*)&sA[k][m0];
      float4 b4 = *(const float4*)&sB[k][n0];
      float a[4] = {a4.x,a4.y,a4.z,a4.w};
      float b2[4] = {b4.x,b4.y,b4.z,b4.w};
      #pragma unroll
      for (int mi = 0; mi < 4; mi++)
        #pragma unroll
        for (int nj = 0; nj < 4; nj++) acc[mi][nj] += a[mi]*b2[nj];
    }
  }
  #pragma unroll
  for (int mi = 0; mi < 4; mi++){
    size_t row = (size_t)mb*64 + m0 + mi;
    #pragma unroll
    for (int nj = 0; nj < 4; nj++){
      int gcol = nb*64 + n0 + nj;
      g_XP[row*NPROJ + gcol] = acc[mi][nj] + bias[nloc + n0 + nj];
    }
  }
}

__global__ void __launch_bounds__(256) k_scan(
    const int* __restrict__ lens,
    const float* __restrict__ whf, const float* __restrict__ whb,
    const float* __restrict__ bhf, const float* __restrict__ bhb,
    float* __restrict__ out){
  extern __shared__ float sm[];
  float* sW  = sm;              // [24][516]
  float* sGH = sm + 24*516;     // [64][24]
  int dir = blockIdx.x & 1, chunk = blockIdx.x >> 1;
  int j0 = chunk*8;
  const float* Wh = dir ? whb : whf;
  const float* bh = dir ? bhb : bhf;
  int tid = threadIdx.x;
  for (int idx = tid; idx < 24*512; idx += 256){
    int r = idx >> 9, k = idx & 511;
    int g = r >> 3, jl = r & 7;
    sW[r*516 + k] = Wh[(size_t)(g*512 + j0 + jl)*512 + k];
  }
  for (int idx = tid; idx < 2*64*8; idx += 256){
    int buf = idx >> 9, bb = (idx >> 3) & 63, jl = idx & 7;
    g_h[buf][dir][bb][j0+jl] = 0.f;
  }
  gbar();
  int bq = tid >> 2, grp = tid & 3;
  for (int t = 0; t < S; t++){
    int rb = t & 1;
    float acc[6] = {0,0,0,0,0,0};
    const float4* hp = reinterpret_cast<const float4*>(&g_h[rb][dir][bq][0]);
    #pragma unroll 4
    for (int k4 = 0; k4 < 128; k4++){
      float4 hv = __ldcg(&hp[k4]);
      #pragma unroll
      for (int i = 0; i < 6; i++){
        const float4 wv = *(const float4*)&sW[(grp*6+i)*516 + k4*4];
        acc[i] += hv.x*wv.x + hv.y*wv.y + hv.z*wv.z + hv.w*wv.w;
      }
    }
    #pragma unroll
    for (int i = 0; i < 6; i++) sGH[bq*24 + grp*6 + i] = acc[i];
    __syncthreads();
    #pragma unroll
    for (int q = 0; q < 2; q++){
      int idx = tid + q*256;
      int bb = idx >> 3, jl = idx & 7;
      int L = lens[bb];
      int j = j0 + jl;
      float hold = __ldcg(&g_h[rb][dir][bb][j]);
      float hnew = hold;
      if (t < L){
        int pos = dir ? (L-1-t) : t;
        size_t xb = ((size_t)bb*S + pos)*NPROJ + (size_t)dir*1536;
        float xr = g_XP[xb + j], xz = g_XP[xb + 512 + j], xn = g_XP[xb + 1024 + j];
        float gr = sGH[bb*24 + jl]      + bh[j];
        float gz = sGH[bb*24 + 8 + jl]  + bh[512 + j];
        float gn = sGH[bb*24 + 16 + jl] + bh[1024 + j];
        float rg = 1.f/(1.f + expf(-(xr+gr)));
        float zg = 1.f/(1.f + expf(-(xz+gz)));
        float ng = tanhf(xn + rg*gn);
        hnew = (1.f - zg)*ng + zg*hold;
        g_ctx[((size_t)bb*S + pos)*1024 + (size_t)dir*512 + j] = hnew;
      }
      g_h[1-rb][dir][bb][j] = hnew;
    }
    gbar();
  }
  for (int idx = tid; idx < 512; idx += 256){
    int bb = idx >> 3, jl = idx & 7;
    out[POOL + (size_t)dir*B*H + (size_t)bb*H + j0 + jl] = g_h[0][dir][bb][j0+jl];
  }
}

__global__ void k_segmax(const int* __restrict__ layout, float* __restrict__ out){
  int bs = blockIdx.x;                 // b*NSEG + s
  int b = bs >> 6, s = bs & 63;
  int lo = layout[b*(NSEG+1) + s], hi = layout[b*(NSEG+1) + s + 1];
  int tid = threadIdx.x;
  #pragma unroll
  for (int q = 0; q < 4; q++){
    int c = tid + q*256;
    float m = -INFINITY;
    for (int t = lo; t < hi; t++)
      m = fmaxf(m, g_ctx[((size_t)b*S + t)*1024 + c]);
    out[(size_t)bs*1024 + c] = m;
  }
}

extern "C" void kernel_launch(void* const* d_in, const int* in_sizes, int n_in,
                              void* d_out, int out_size){
  (void)in_sizes; (void)n_in; (void)out_size;
  const int*   seq    = (const int*)d_in[0];
  const int*   lens   = (const int*)d_in[1];
  const int*   layout = (const int*)d_in[3];
  const float* emb    = (const float*)d_in[4];
  const float* wif    = (const float*)d_in[5];
  const float* whf    = (const float*)d_in[6];
  const float* bif    = (const float*)d_in[7];
  const float* bhf    = (const float*)d_in[8];
  const float* wib    = (const float*)d_in[9];
  const float* whb    = (const float*)d_in[10];
  const float* bib    = (const float*)d_in[11];
  const float* bhb    = (const float*)d_in[12];
  float* out = (float*)d_out;
  (void)bif; (void)bib;

  k_embed<<<MR*128/256, 256>>>(seq, emb);
  dim3 gg(48, 512);
  k_gemm<<<gg, 256>>>(wif, wib, bif, bib);
  int smem = (24*516 + 64*24)*4;
  cudaFuncSetAttribute(k_scan, cudaFuncAttributeMaxDynamicSharedMemorySize, smem);
  k_scan<<<NBLK, 256, smem>>>(lens, whf, whb, bhf, bhb, out);
  k_segmax<<<B*NSEG, 256>>>(layout, out);
}

// round 12
// speedup vs baseline: 2.0598x; 2.0598x over previous
#include <cuda_runtime.h>
#include <math.h>

#define B 64
#define S 512
#define H 512
#define E 512
#define NSEG 64
#define MR (B*S)
#define NPROJ 3072
#define POOL (B*NSEG*2*H)
#define NBLK 128

__device__ __align__(16) float g_X[(size_t)MR*E];
__device__ __align__(16) float g_XP[(size_t)MR*NPROJ];
__device__ __align__(16) float g_ctx[(size_t)MR*2*H];
__device__ __align__(16) float g_ht[2][2][H][B];   // [buf][dir][col][batch]
__device__ unsigned long long g_bar;

__device__ __forceinline__ void gbar(){
  __threadfence();
  __syncthreads();
  if (threadIdx.x == 0){
    unsigned long long t = atomicAdd(&g_bar, 1ULL);
    unsigned long long target = (t/(unsigned long long)NBLK + 1ULL)*(unsigned long long)NBLK;
    while (*(volatile unsigned long long*)&g_bar < target) __nanosleep(32);
  }
  __syncthreads();
}

__device__ __forceinline__ unsigned tf(float x){
  unsigned u; asm("cvt.rna.tf32.f32 %0, %1;" : "=r"(u) : "f"(x));
  return u;
}
__device__ __forceinline__ void mma8(float c[4], const unsigned a[4], const unsigned b[2]){
  asm volatile("mma.sync.aligned.m16n8k8.row.col.f32.tf32.tf32.f32 "
    "{%0,%1,%2,%3}, {%4,%5,%6,%7}, {%8,%9}, {%0,%1,%2,%3};"
    : "+f"(c[0]), "+f"(c[1]), "+f"(c[2]), "+f"(c[3])
    : "r"(a[0]), "r"(a[1]), "r"(a[2]), "r"(a[3]), "r"(b[0]), "r"(b[1]));
}
__device__ __forceinline__ unsigned long long pack2(float lo, float hi){
  unsigned long long d;
  asm("mov.b64 %0, {%1, %2};" : "=l"(d) : "f"(lo), "f"(hi));
  return d;
}
__device__ __forceinline__ unsigned long long fma2(unsigned long long a, unsigned long long b, unsigned long long c){
  unsigned long long d;
  asm("fma.rn.f32x2 %0, %1, %2, %3;" : "=l"(d) : "l"(a), "l"(b), "l"(c));
  return d;
}

__global__ void k_embed(const int* __restrict__ seq, const float* __restrict__ emb){
  size_t i = (size_t)blockIdx.x*256 + threadIdx.x;
  int c = (int)(i & 127); size_t row = i >> 7;
  int tok = seq[row];
  reinterpret_cast<float4*>(g_X)[row*128 + c] =
      reinterpret_cast<const float4*>(emb)[(size_t)tok*128 + c];
}

// C[32768,3072] = X @ W^T + b, tf32 tensor cores. Tile 128(M)x64(N), K-step 32.
__global__ void __launch_bounds__(256) k_gemm(
    const float* __restrict__ wf, const float* __restrict__ wb,
    const float* __restrict__ bf, const float* __restrict__ bb){
  __shared__ __align__(16) float sA[128*36];
  __shared__ __align__(16) float sB[64*36];
  int nb = blockIdx.x, mb = blockIdx.y;            // nb 0..47, mb 0..255
  const float* W; const float* bias; int nloc;
  if (nb < 24){ W = wf; bias = bf; nloc = nb*64; }
  else        { W = wb; bias = bb; nloc = (nb-24)*64; }
  int tid = threadIdx.x, lane = tid & 31, warp = tid >> 5;
  int wM = warp & 3, wN = warp >> 2;
  float acc[2][4][4];
  #pragma unroll
  for (int i=0;i<2;i++)
    #pragma unroll
    for (int j=0;j<4;j++)
      #pragma unroll
      for (int k=0;k<4;k++) acc[i][j][k]=0.f;
  const float4* X4 = reinterpret_cast<const float4*>(g_X);
  const float4* W4 = reinterpret_cast<const float4*>(W);
  for (int kt = 0; kt < 16; kt++){
    float4 av[4], bv[2];
    #pragma unroll
    for (int it=0; it<4; it++){
      int idx = tid + it*256, r = idx>>3, c4 = idx&7;
      av[it] = X4[((size_t)(mb*128+r))*128 + kt*8 + c4];
    }
    #pragma unroll
    for (int it=0; it<2; it++){
      int idx = tid + it*256, r = idx>>3, c4 = idx&7;
      bv[it] = W4[((size_t)(nloc+r))*128 + kt*8 + c4];
    }
    __syncthreads();
    unsigned* uA = (unsigned*)sA; unsigned* uB = (unsigned*)sB;
    #pragma unroll
    for (int it=0; it<4; it++){
      int idx = tid + it*256, r = idx>>3, c4 = idx&7;
      unsigned* d = uA + r*36 + c4*4;
      d[0]=tf(av[it].x); d[1]=tf(av[it].y); d[2]=tf(av[it].z); d[3]=tf(av[it].w);
    }
    #pragma unroll
    for (int it=0; it<2; it++){
      int idx = tid + it*256, r = idx>>3, c4 = idx&7;
      unsigned* d = uB + r*36 + c4*4;
      d[0]=tf(bv[it].x); d[1]=tf(bv[it].y); d[2]=tf(bv[it].z); d[3]=tf(bv[it].w);
    }
    __syncthreads();
    #pragma unroll
    for (int ks=0; ks<4; ks++){
      int kb = ks*8;
      unsigned afr[2][4], bfr[4][2];
      #pragma unroll
      for (int wm=0; wm<2; wm++){
        int r = wM*32 + wm*16 + (lane>>2), c = kb + (lane&3);
        afr[wm][0] = uA[r*36 + c];       afr[wm][1] = uA[(r+8)*36 + c];
        afr[wm][2] = uA[r*36 + c + 4];   afr[wm][3] = uA[(r+8)*36 + c + 4];
      }
      #pragma unroll
      for (int wn=0; wn<4; wn++){
        int nr = wN*32 + wn*8 + (lane>>2), c = kb + (lane&3);
        bfr[wn][0] = uB[nr*36 + c]; bfr[wn][1] = uB[nr*36 + c + 4];
      }
      #pragma unroll
      for (int wm=0; wm<2; wm++)
        #pragma unroll
        for (int wn=0; wn<4; wn++) mma8(acc[wm][wn], afr[wm], bfr[wn]);
    }
    __syncthreads();
  }
  #pragma unroll
  for (int wm=0; wm<2; wm++){
    int r0 = mb*128 + wM*32 + wm*16 + (lane>>2);
    #pragma unroll
    for (int wn=0; wn<4; wn++){
      int cl = wN*32 + wn*8 + (lane&3)*2;
      int cg = nb*64 + cl;
      float b0v = bias[nloc + cl], b1v = bias[nloc + cl + 1];
      float2 v0 = make_float2(acc[wm][wn][0]+b0v, acc[wm][wn][1]+b1v);
      float2 v1 = make_float2(acc[wm][wn][2]+b0v, acc[wm][wn][3]+b1v);
      *(float2*)&g_XP[(size_t)r0*NPROJ + cg] = v0;
      *(float2*)&g_XP[(size_t)(r0+8)*NPROJ + cg] = v1;
    }
  }
}

// Persistent bidirectional GRU scan. 128 blocks = 2 dirs x 64 col-chunks (8 h-cols, 24 gate rows).
__global__ void __launch_bounds__(256, 1) k_scan(
    const int* __restrict__ lens,
    const float* __restrict__ whf, const float* __restrict__ whb,
    const float* __restrict__ bhf, const float* __restrict__ bhb,
    float* __restrict__ out){
  extern __shared__ float sm[];
  float* sW = sm;                    // [24][516]
  float* sH = sm + 24*516;           // [128][68]
  float* sP = sH + 128*68;           // [1536][8] partials
  float* sG = sP + 1536*8;           // [64][24]
  int dir = blockIdx.x & 1, chunk = blockIdx.x >> 1;
  int j0 = chunk*8;
  const float* Wh = dir ? whb : whf;
  const float* bh = dir ? bhb : bhf;
  int tid = threadIdx.x;
  for (int idx = tid; idx < 24*512; idx += 256){
    int r = idx >> 9, k = idx & 511;
    sW[r*516 + k] = Wh[(size_t)((r>>3)*512 + j0 + (r&7))*512 + k];
  }
  for (int idx = tid; idx < 1024; idx += 256){
    int buf = idx >> 9, jl = (idx >> 6) & 7, bb = idx & 63;
    g_ht[buf][dir][j0+jl][bb] = 0.f;
  }
  // update-phase identity: same batch for both halves, jl0 and jl0+4
  int jl0 = tid >> 6, bb0 = tid & 63;
  float b_r0 = bh[j0+jl0],   b_z0 = bh[512+j0+jl0],   b_n0 = bh[1024+j0+jl0];
  float b_r1 = bh[j0+jl0+4], b_z1 = bh[512+j0+jl0+4], b_n1 = bh[1024+j0+jl0+4];
  int L_u = __ldg(&lens[bb0]);
  // matvec identity
  int bg = tid >> 5, rg = (tid >> 3) & 3, ks = tid & 7;
  int b0 = bg*8, r0 = rg*6;
  gbar();
  float hn0 = 0.f, hn1 = 0.f;
  for (int t = 0; t < S; t++){
    int rb = t & 1, wb = 1 - rb;
    // prefetch xp + h_old (hidden under matvec)
    bool v = (t < L_u);
    int pos = dir ? (L_u-1-t) : t;
    float xr0=0,xz0=0,xn0=0,xr1=0,xz1=0,xn1=0;
    if (v){
      size_t xb = ((size_t)bb0*S + pos)*NPROJ + (size_t)dir*1536 + j0;
      xr0 = __ldg(&g_XP[xb + jl0]);        xr1 = __ldg(&g_XP[xb + jl0 + 4]);
      xz0 = __ldg(&g_XP[xb + 512 + jl0]);  xz1 = __ldg(&g_XP[xb + 512 + jl0 + 4]);
      xn0 = __ldg(&g_XP[xb + 1024 + jl0]); xn1 = __ldg(&g_XP[xb + 1024 + jl0 + 4]);
    }
    float hold0 = __ldcg(&g_ht[rb][dir][j0+jl0][bb0]);
    float hold1 = __ldcg(&g_ht[rb][dir][j0+jl0+4][bb0]);
    unsigned long long acc[6][4];
    #pragma unroll
    for (int rr=0; rr<6; rr++)
      #pragma unroll
      for (int p=0; p<4; p++) acc[rr][p] = 0ULL;
    for (int kc = 0; kc < 4; kc++){
      __syncthreads();
      #pragma unroll
      for (int q2 = 0; q2 < 8; q2++){
        int idx = tid + q2*256;
        int kr = idx >> 4, b4 = idx & 15;
        float4 vv = __ldcg(reinterpret_cast<const float4*>(&g_ht[rb][dir][kc*128+kr][0]) + b4);
        *(float4*)&sH[kr*68 + b4*4] = vv;
      }
      __syncthreads();
      #pragma unroll 4
      for (int i = 0; i < 16; i++){
        int kl = i*8 + ks;
        int kg = kc*128 + kl;
        float4 h1 = *(const float4*)&sH[kl*68 + b0];
        float4 h2 = *(const float4*)&sH[kl*68 + b0 + 4];
        unsigned long long hp0 = pack2(h1.x,h1.y), hp1 = pack2(h1.z,h1.w);
        unsigned long long hp2 = pack2(h2.x,h2.y), hp3 = pack2(h2.z,h2.w);
        #pragma unroll
        for (int rr = 0; rr < 6; rr++){
          float w = sW[(r0+rr)*516 + kg];
          unsigned long long wd = pack2(w,w);
          acc[rr][0] = fma2(hp0, wd, acc[rr][0]);
          acc[rr][1] = fma2(hp1, wd, acc[rr][1]);
          acc[rr][2] = fma2(hp2, wd, acc[rr][2]);
          acc[rr][3] = fma2(hp3, wd, acc[rr][3]);
        }
      }
    }
    #pragma unroll
    for (int rr=0; rr<6; rr++)
      #pragma unroll
      for (int p=0; p<4; p++){
        float lo = __uint_as_float((unsigned)(acc[rr][p] & 0xffffffffULL));
        float hi = __uint_as_float((unsigned)(acc[rr][p] >> 32));
        int ob = (r0+rr)*64 + b0 + 2*p;
        sP[ob*8 + ks] = lo;
        sP[(ob+1)*8 + ks] = hi;
      }
    __syncthreads();
    #pragma unroll
    for (int m = 0; m < 6; m++){
      int o = tid*6 + m;
      float4 a4 = *(const float4*)&sP[o*8];
      float4 c4 = *(const float4*)&sP[o*8+4];
      float s = ((a4.x+a4.y)+(a4.z+a4.w)) + ((c4.x+c4.y)+(c4.z+c4.w));
      sG[(o & 63)*24 + (o >> 6)] = s;
    }
    __syncthreads();
    hn0 = hold0; hn1 = hold1;
    if (v){
      float gr = sG[bb0*24 + jl0]      + b_r0;
      float gz = sG[bb0*24 + 8 + jl0]  + b_z0;
      float gn = sG[bb0*24 + 16 + jl0] + b_n0;
      float rr = 1.f/(1.f+expf(-(xr0+gr)));
      float zz = 1.f/(1.f+expf(-(xz0+gz)));
      float nn = tanhf(xn0 + rr*gn);
      hn0 = (1.f-zz)*nn + zz*hold0;
      g_ctx[((size_t)bb0*S+pos)*1024 + (size_t)dir*512 + j0 + jl0] = hn0;
      gr = sG[bb0*24 + jl0 + 4]      + b_r1;
      gz = sG[bb0*24 + 8 + jl0 + 4]  + b_z1;
      gn = sG[bb0*24 + 16 + jl0 + 4] + b_n1;
      rr = 1.f/(1.f+expf(-(xr1+gr)));
      zz = 1.f/(1.f+expf(-(xz1+gz)));
      nn = tanhf(xn1 + rr*gn);
      hn1 = (1.f-zz)*nn + zz*hold1;
      g_ctx[((size_t)bb0*S+pos)*1024 + (size_t)dir*512 + j0 + jl0 + 4] = hn1;
    }
    g_ht[wb][dir][j0+jl0][bb0] = hn0;
    g_ht[wb][dir][j0+jl0+4][bb0] = hn1;
    gbar();
  }
  out[POOL + (size_t)dir*B*H + (size_t)bb0*H + j0 + jl0]     = hn0;
  out[POOL + (size_t)dir*B*H + (size_t)bb0*H + j0 + jl0 + 4] = hn1;
}

__global__ void k_segmax(const int* __restrict__ layout, float* __restrict__ out){
  int bs = blockIdx.x;
  int b = bs >> 6, s = bs & 63;
  int lo = layout[b*(NSEG+1) + s], hi = layout[b*(NSEG+1) + s + 1];
  int tid = threadIdx.x;
  #pragma unroll
  for (int q = 0; q < 4; q++){
    int c = tid + q*256;
    float m = -INFINITY;
    for (int t = lo; t < hi; t++)
      m = fmaxf(m, g_ctx[((size_t)b*S + t)*1024 + c]);
    out[(size_t)bs*1024 + c] = m;
  }
}

extern "C" void kernel_launch(void* const* d_in, const int* in_sizes, int n_in,
                              void* d_out, int out_size){
  (void)in_sizes; (void)n_in; (void)out_size;
  const int*   seq    = (const int*)d_in[0];
  const int*   lens   = (const int*)d_in[1];
  const int*   layout = (const int*)d_in[3];
  const float* emb    = (const float*)d_in[4];
  const float* wif    = (const float*)d_in[5];
  const float* whf    = (const float*)d_in[6];
  const float* bif    = (const float*)d_in[7];
  const float* bhf    = (const float*)d_in[8];
  const float* wib    = (const float*)d_in[9];
  const float* whb    = (const float*)d_in[10];
  const float* bib    = (const float*)d_in[11];
  const float* bhb    = (const float*)d_in[12];
  float* out = (float*)d_out;

  k_embed<<<MR*128/256, 256>>>(seq, emb);
  dim3 gg(48, 256);
  k_gemm<<<gg, 256>>>(wif, wib, bif, bib);
  int smem = (24*516 + 128*68 + 1536*8 + 1536)*4;
  cudaFuncSetAttribute(k_scan, cudaFuncAttributeMaxDynamicSharedMemorySize, smem);
  k_scan<<<NBLK, 256, smem>>>(lens, whf, whb, bhf, bhb, out);
  k_segmax<<<B*NSEG, 256>>>(layout, out);
}

// round 14
// speedup vs baseline: 2.1574x; 1.0474x over previous
#include <cuda_runtime.h>
#include <math.h>

#define B 64
#define S 512
#define H 512
#define E 512
#define NSEG 64
#define MR (B*S)
#define NPROJ 3072
#define POOL (B*NSEG*2*H)
#define NBLK 128

__device__ __align__(16) float g_X[(size_t)MR*E];
__device__ __align__(16) float g_XP[(size_t)MR*NPROJ];
__device__ __align__(16) float g_ctx[(size_t)MR*2*H];
__device__ __align__(16) float g_ht[2][2][H][B];   // [buf][dir][col][batch]
__device__ unsigned long long g_bar;

__device__ __forceinline__ void gbar(){
  __threadfence();
  __syncthreads();
  if (threadIdx.x == 0){
    unsigned long long t = atomicAdd(&g_bar, 1ULL);
    unsigned long long target = (t/(unsigned long long)NBLK + 1ULL)*(unsigned long long)NBLK;
    while (*(volatile unsigned long long*)&g_bar < target) __nanosleep(32);
  }
  __syncthreads();
}

__device__ __forceinline__ unsigned tf(float x){
  unsigned u; asm("cvt.rna.tf32.f32 %0, %1;" : "=r"(u) : "f"(x));
  return u;
}
__device__ __forceinline__ void mma8(float c[4], const unsigned a[4], const unsigned b[2]){
  asm volatile("mma.sync.aligned.m16n8k8.row.col.f32.tf32.tf32.f32 "
    "{%0,%1,%2,%3}, {%4,%5,%6,%7}, {%8,%9}, {%0,%1,%2,%3};"
    : "+f"(c[0]), "+f"(c[1]), "+f"(c[2]), "+f"(c[3])
    : "r"(a[0]), "r"(a[1]), "r"(a[2]), "r"(a[3]), "r"(b[0]), "r"(b[1]));
}
__device__ __forceinline__ unsigned long long pack2(float lo, float hi){
  unsigned long long d;
  asm("mov.b64 %0, {%1, %2};" : "=l"(d) : "f"(lo), "f"(hi));
  return d;
}
__device__ __forceinline__ unsigned long long fma2(unsigned long long a, unsigned long long b, unsigned long long c){
  unsigned long long d;
  asm("fma.rn.f32x2 %0, %1, %2, %3;" : "=l"(d) : "l"(a), "l"(b), "l"(c));
  return d;
}
__device__ __forceinline__ void cpasync16(unsigned saddr, const void* g){
  asm volatile("cp.async.cg.shared.global [%0], [%1], 16;" :: "r"(saddr), "l"(g) : "memory");
}

__global__ void k_embed(const int* __restrict__ seq, const float* __restrict__ emb){
  size_t i = (size_t)blockIdx.x*256 + threadIdx.x;
  int c = (int)(i & 127); size_t row = i >> 7;
  int tok = seq[row];
  reinterpret_cast<float4*>(g_X)[row*128 + c] =
      reinterpret_cast<const float4*>(emb)[(size_t)tok*128 + c];
}

__global__ void __launch_bounds__(256) k_gemm(
    const float* __restrict__ wf, const float* __restrict__ wb,
    const float* __restrict__ bf, const float* __restrict__ bb){
  __shared__ __align__(16) float sA[128*36];
  __shared__ __align__(16) float sB[64*36];
  int nb = blockIdx.x, mb = blockIdx.y;
  const float* W; const float* bias; int nloc;
  if (nb < 24){ W = wf; bias = bf; nloc = nb*64; }
  else        { W = wb; bias = bb; nloc = (nb-24)*64; }
  int tid = threadIdx.x, lane = tid & 31, warp = tid >> 5;
  int wM = warp & 3, wN = warp >> 2;
  float acc[2][4][4];
  #pragma unroll
  for (int i=0;i<2;i++)
    #pragma unroll
    for (int j=0;j<4;j++)
      #pragma unroll
      for (int k=0;k<4;k++) acc[i][j][k]=0.f;
  const float4* X4 = reinterpret_cast<const float4*>(g_X);
  const float4* W4 = reinterpret_cast<const float4*>(W);
  for (int kt = 0; kt < 16; kt++){
    float4 av[4], bv[2];
    #pragma unroll
    for (int it=0; it<4; it++){
      int idx = tid + it*256, r = idx>>3, c4 = idx&7;
      av[it] = X4[((size_t)(mb*128+r))*128 + kt*8 + c4];
    }
    #pragma unroll
    for (int it=0; it<2; it++){
      int idx = tid + it*256, r = idx>>3, c4 = idx&7;
      bv[it] = W4[((size_t)(nloc+r))*128 + kt*8 + c4];
    }
    __syncthreads();
    unsigned* uA = (unsigned*)sA; unsigned* uB = (unsigned*)sB;
    #pragma unroll
    for (int it=0; it<4; it++){
      int idx = tid + it*256, r = idx>>3, c4 = idx&7;
      unsigned* d = uA + r*36 + c4*4;
      d[0]=tf(av[it].x); d[1]=tf(av[it].y); d[2]=tf(av[it].z); d[3]=tf(av[it].w);
    }
    #pragma unroll
    for (int it=0; it<2; it++){
      int idx = tid + it*256, r = idx>>3, c4 = idx&7;
      unsigned* d = uB + r*36 + c4*4;
      d[0]=tf(bv[it].x); d[1]=tf(bv[it].y); d[2]=tf(bv[it].z); d[3]=tf(bv[it].w);
    }
    __syncthreads();
    #pragma unroll
    for (int ks=0; ks<4; ks++){
      int kb = ks*8;
      unsigned afr[2][4], bfr[4][2];
      #pragma unroll
      for (int wm=0; wm<2; wm++){
        int r = wM*32 + wm*16 + (lane>>2), c = kb + (lane&3);
        afr[wm][0] = uA[r*36 + c];       afr[wm][1] = uA[(r+8)*36 + c];
        afr[wm][2] = uA[r*36 + c + 4];   afr[wm][3] = uA[(r+8)*36 + c + 4];
      }
      #pragma unroll
      for (int wn=0; wn<4; wn++){
        int nr = wN*32 + wn*8 + (lane>>2), c = kb + (lane&3);
        bfr[wn][0] = uB[nr*36 + c]; bfr[wn][1] = uB[nr*36 + c + 4];
      }
      #pragma unroll
      for (int wm=0; wm<2; wm++)
        #pragma unroll
        for (int wn=0; wn<4; wn++) mma8(acc[wm][wn], afr[wm], bfr[wn]);
    }
    __syncthreads();
  }
  #pragma unroll
  for (int wm=0; wm<2; wm++){
    int r0 = mb*128 + wM*32 + wm*16 + (lane>>2);
    #pragma unroll
    for (int wn=0; wn<4; wn++){
      int cl = wN*32 + wn*8 + (lane&3)*2;
      int cg = nb*64 + cl;
      float b0v = bias[nloc + cl], b1v = bias[nloc + cl + 1];
      float2 v0 = make_float2(acc[wm][wn][0]+b0v, acc[wm][wn][1]+b1v);
      float2 v1 = make_float2(acc[wm][wn][2]+b0v, acc[wm][wn][3]+b1v);
      *(float2*)&g_XP[(size_t)r0*NPROJ + cg] = v0;
      *(float2*)&g_XP[(size_t)(r0+8)*NPROJ + cg] = v1;
    }
  }
}

// Persistent bidirectional GRU scan. 128 blocks = 2 dirs x 64 col-chunks.
// smem: sW [24][516] | sH [512][68] | sP [1536][4] | sG [1536]
__global__ void __launch_bounds__(256, 1) k_scan(
    const int* __restrict__ lens,
    const float* __restrict__ whf, const float* __restrict__ whb,
    const float* __restrict__ bhf, const float* __restrict__ bhb,
    float* __restrict__ out){
  extern __shared__ float sm[];
  float* sW = sm;                    // 12384 floats
  float* sH = sm + 24*516;           // 34816 floats
  float* sP = sH + 512*68;           // 6144 floats
  float* sG = sP + 1536*4;           // 1536 floats
  int dir = blockIdx.x & 1, chunk = blockIdx.x >> 1;
  int j0 = chunk*8;
  const float* Wh = dir ? whb : whf;
  const float* bh = dir ? bhb : bhf;
  int tid = threadIdx.x;
  for (int idx = tid; idx < 24*512; idx += 256){
    int r = idx >> 9, k = idx & 511;
    sW[r*516 + k] = Wh[(size_t)((r>>3)*512 + j0 + (r&7))*512 + k];
  }
  for (int idx = tid; idx < 1024; idx += 256){
    int buf = idx >> 9, jl = (idx >> 6) & 7, bb = idx & 63;
    g_ht[buf][dir][j0+jl][bb] = 0.f;
  }
  // update-phase identity
  int jl0 = tid >> 6, bb0 = tid & 63;
  float b_r0 = bh[j0+jl0],   b_z0 = bh[512+j0+jl0],   b_n0 = bh[1024+j0+jl0];
  float b_r1 = bh[j0+jl0+4], b_z1 = bh[512+j0+jl0+4], b_n1 = bh[1024+j0+jl0+4];
  int L_u = __ldg(&lens[bb0]);
  // matvec identity: warp=bg (8 batches), rg (3 rows), ks (K mod 4)
  int bg = tid >> 5, rg = (tid >> 2) & 7, ks = tid & 3;
  int b0 = bg*8, r0 = rg*3;
  unsigned sH_base = (unsigned)__cvta_generic_to_shared(sH);
  gbar();
  float hn0 = 0.f, hn1 = 0.f;
  for (int t = 0; t < S; t++){
    int rb = t & 1, wb = 1 - rb;
    // prefetch xp (hidden under matvec)
    bool v = (t < L_u);
    int pos = dir ? (L_u-1-t) : t;
    float xr0=0,xz0=0,xn0=0,xr1=0,xz1=0,xn1=0;
    if (v){
      size_t xb = ((size_t)bb0*S + pos)*NPROJ + (size_t)dir*1536 + j0;
      xr0 = __ldg(&g_XP[xb + jl0]);        xr1 = __ldg(&g_XP[xb + jl0 + 4]);
      xz0 = __ldg(&g_XP[xb + 512 + jl0]);  xz1 = __ldg(&g_XP[xb + 512 + jl0 + 4]);
      xn0 = __ldg(&g_XP[xb + 1024 + jl0]); xn1 = __ldg(&g_XP[xb + 1024 + jl0 + 4]);
    }
    // stage full h into sH: 4 commit groups, each 128 rows x 64 batches = 2048 float4
    #pragma unroll
    for (int g = 0; g < 4; g++){
      #pragma unroll
      for (int q = 0; q < 8; q++){
        int idx = q*256 + tid;
        int k = g*128 + (idx >> 4), b4 = idx & 15;
        cpasync16(sH_base + (unsigned)(k*68 + b4*4)*4u, &g_ht[rb][dir][k][b4*4]);
      }
      asm volatile("cp.async.commit_group;" ::: "memory");
    }
    unsigned long long acc[3][4];
    #pragma unroll
    for (int rr=0; rr<3; rr++)
      #pragma unroll
      for (int p=0; p<4; p++) acc[rr][p] = 0ULL;
    #pragma unroll
    for (int c = 0; c < 4; c++){
      if (c==0)      asm volatile("cp.async.wait_group 3;" ::: "memory");
      else if (c==1) asm volatile("cp.async.wait_group 2;" ::: "memory");
      else if (c==2) asm volatile("cp.async.wait_group 1;" ::: "memory");
      else           asm volatile("cp.async.wait_group 0;" ::: "memory");
      __syncthreads();
      #pragma unroll 4
      for (int i = 0; i < 32; i++){
        int kg = c*128 + i*4 + ks;
        float4 h1 = *(const float4*)&sH[kg*68 + b0];
        float4 h2 = *(const float4*)&sH[kg*68 + b0 + 4];
        unsigned long long hp0 = pack2(h1.x,h1.y), hp1 = pack2(h1.z,h1.w);
        unsigned long long hp2 = pack2(h2.x,h2.y), hp3 = pack2(h2.z,h2.w);
        #pragma unroll
        for (int rr = 0; rr < 3; rr++){
          float w = sW[(r0+rr)*516 + kg];
          unsigned long long wd = pack2(w,w);
          acc[rr][0] = fma2(hp0, wd, acc[rr][0]);
          acc[rr][1] = fma2(hp1, wd, acc[rr][1]);
          acc[rr][2] = fma2(hp2, wd, acc[rr][2]);
          acc[rr][3] = fma2(hp3, wd, acc[rr][3]);
        }
      }
    }
    // h_old from staged sH (fully resident after wait_group 0)
    float hold0 = sH[(j0+jl0)*68 + bb0];
    float hold1 = sH[(j0+jl0+4)*68 + bb0];
    // write K-partials: index (b*24 + r)*4 + ks
    #pragma unroll
    for (int rr=0; rr<3; rr++)
      #pragma unroll
      for (int p=0; p<4; p++){
        float lo = __uint_as_float((unsigned)(acc[rr][p] & 0xffffffffULL));
        float hi = __uint_as_float((unsigned)(acc[rr][p] >> 32));
        int r = r0 + rr;
        int ba = b0 + 2*p;
        sP[((ba)*24 + r)*4 + ks]   = lo;
        sP[((ba+1)*24 + r)*4 + ks] = hi;
      }
    __syncthreads();
    // reduce 4 partials -> sG[b*24+r]
    #pragma unroll
    for (int m = 0; m < 6; m++){
      int o = tid*6 + m;
      float4 a4 = *(const float4*)&sP[o*4];
      sG[o] = (a4.x + a4.y) + (a4.z + a4.w);
    }
    __syncthreads();
    hn0 = hold0; hn1 = hold1;
    if (v){
      float gr = sG[bb0*24 + jl0]      + b_r0;
      float gz = sG[bb0*24 + 8 + jl0]  + b_z0;
      float gn = sG[bb0*24 + 16 + jl0] + b_n0;
      float rr = 1.f/(1.f+expf(-(xr0+gr)));
      float zz = 1.f/(1.f+expf(-(xz0+gz)));
      float nn = tanhf(xn0 + rr*gn);
      hn0 = (1.f-zz)*nn + zz*hold0;
      g_ctx[((size_t)bb0*S+pos)*1024 + (size_t)dir*512 + j0 + jl0] = hn0;
      gr = sG[bb0*24 + jl0 + 4]      + b_r1;
      gz = sG[bb0*24 + 8 + jl0 + 4]  + b_z1;
      gn = sG[bb0*24 + 16 + jl0 + 4] + b_n1;
      rr = 1.f/(1.f+expf(-(xr1+gr)));
      zz = 1.f/(1.f+expf(-(xz1+gz)));
      nn = tanhf(xn1 + rr*gn);
      hn1 = (1.f-zz)*nn + zz*hold1;
      g_ctx[((size_t)bb0*S+pos)*1024 + (size_t)dir*512 + j0 + jl0 + 4] = hn1;
    }
    g_ht[wb][dir][j0+jl0][bb0] = hn0;
    g_ht[wb][dir][j0+jl0+4][bb0] = hn1;
    gbar();
  }
  out[POOL + (size_t)dir*B*H + (size_t)bb0*H + j0 + jl0]     = hn0;
  out[POOL + (size_t)dir*B*H + (size_t)bb0*H + j0 + jl0 + 4] = hn1;
}

__global__ void k_segmax(const int* __restrict__ layout, float* __restrict__ out){
  int bs = blockIdx.x;
  int b = bs >> 6, s = bs & 63;
  int lo = layout[b*(NSEG+1) + s], hi = layout[b*(NSEG+1) + s + 1];
  int tid = threadIdx.x;
  #pragma unroll
  for (int q = 0; q < 4; q++){
    int c = tid + q*256;
    float m = -INFINITY;
    for (int t = lo; t < hi; t++)
      m = fmaxf(m, g_ctx[((size_t)b*S + t)*1024 + c]);
    out[(size_t)bs*1024 + c] = m;
  }
}

extern "C" void kernel_launch(void* const* d_in, const int* in_sizes, int n_in,
                              void* d_out, int out_size){
  (void)in_sizes; (void)n_in; (void)out_size;
  const int*   seq    = (const int*)d_in[0];
  const int*   lens   = (const int*)d_in[1];
  const int*   layout = (const int*)d_in[3];
  const float* emb    = (const float*)d_in[4];
  const float* wif    = (const float*)d_in[5];
  const float* whf    = (const float*)d_in[6];
  const float* bif    = (const float*)d_in[7];
  const float* bhf    = (const float*)d_in[8];
  const float* wib    = (const float*)d_in[9];
  const float* whb    = (const float*)d_in[10];
  const float* bib    = (const float*)d_in[11];
  const float* bhb    = (const float*)d_in[12];
  float* out = (float*)d_out;

  k_embed<<<MR*128/256, 256>>>(seq, emb);
  dim3 gg(48, 256);
  k_gemm<<<gg, 256>>>(wif, wib, bif, bib);
  int smem = (24*516 + 512*68 + 1536*4 + 1536)*4;
  cudaFuncSetAttribute(k_scan, cudaFuncAttributeMaxDynamicSharedMemorySize, smem);
  k_scan<<<NBLK, 256, smem>>>(lens, whf, whb, bhf, bhb, out);
  k_segmax<<<B*NSEG, 256>>>(layout, out);
}

// round 15
// speedup vs baseline: 3.1630x; 1.4661x over previous
#include <cuda_runtime.h>
#include <math.h>

#define B 64
#define S 512
#define H 512
#define E 512
#define NSEG 64
#define MR (B*S)
#define NPROJ 3072
#define POOL (B*NSEG*2*H)
#define NBLKD 64   // blocks per direction

__device__ __align__(16) float g_X[(size_t)MR*E];
__device__ __align__(16) float g_XP[(size_t)MR*NPROJ];
__device__ __align__(16) float g_ctx[(size_t)MR*2*H];
__device__ __align__(16) float g_ht[2][2][H][B];   // [buf][dir][col][batch]
__device__ unsigned long long g_bar2[64];          // [dir*32]

__device__ __forceinline__ void gbar(int dir){
  __threadfence();
  __syncthreads();
  if (threadIdx.x == 0){
    unsigned long long* p = &g_bar2[dir*32];
    unsigned long long t = atomicAdd(p, 1ULL);
    unsigned long long target = (t/(unsigned long long)NBLKD + 1ULL)*(unsigned long long)NBLKD;
    while (*(volatile unsigned long long*)p < target) __nanosleep(16);
  }
  __syncthreads();
}

__device__ __forceinline__ unsigned tf(float x){
  unsigned u; asm("cvt.rna.tf32.f32 %0, %1;" : "=r"(u) : "f"(x));
  return u;
}
__device__ __forceinline__ void mma8(float c[4], const unsigned a[4], const unsigned b[2]){
  asm volatile("mma.sync.aligned.m16n8k8.row.col.f32.tf32.tf32.f32 "
    "{%0,%1,%2,%3}, {%4,%5,%6,%7}, {%8,%9}, {%0,%1,%2,%3};"
    : "+f"(c[0]), "+f"(c[1]), "+f"(c[2]), "+f"(c[3])
    : "r"(a[0]), "r"(a[1]), "r"(a[2]), "r"(a[3]), "r"(b[0]), "r"(b[1]));
}
__device__ __forceinline__ void cpasync16(unsigned saddr, const void* g){
  asm volatile("cp.async.cg.shared.global [%0], [%1], 16;" :: "r"(saddr), "l"(g) : "memory");
}

__global__ void k_embed(const int* __restrict__ seq, const float* __restrict__ emb){
  size_t i = (size_t)blockIdx.x*256 + threadIdx.x;
  int c = (int)(i & 127); size_t row = i >> 7;
  int tok = seq[row];
  reinterpret_cast<float4*>(g_X)[row*128 + c] =
      reinterpret_cast<const float4*>(emb)[(size_t)tok*128 + c];
}

__global__ void __launch_bounds__(256) k_gemm(
    const float* __restrict__ wf, const float* __restrict__ wb,
    const float* __restrict__ bf, const float* __restrict__ bb){
  __shared__ __align__(16) float sA[128*36];
  __shared__ __align__(16) float sB[64*36];
  int nb = blockIdx.x, mb = blockIdx.y;
  const float* W; const float* bias; int nloc;
  if (nb < 24){ W = wf; bias = bf; nloc = nb*64; }
  else        { W = wb; bias = bb; nloc = (nb-24)*64; }
  int tid = threadIdx.x, lane = tid & 31, warp = tid >> 5;
  int wM = warp & 3, wN = warp >> 2;
  float acc[2][4][4];
  #pragma unroll
  for (int i=0;i<2;i++)
    #pragma unroll
    for (int j=0;j<4;j++)
      #pragma unroll
      for (int k=0;k<4;k++) acc[i][j][k]=0.f;
  const float4* X4 = reinterpret_cast<const float4*>(g_X);
  const float4* W4 = reinterpret_cast<const float4*>(W);
  for (int kt = 0; kt < 16; kt++){
    float4 av[4], bv[2];
    #pragma unroll
    for (int it=0; it<4; it++){
      int idx = tid + it*256, r = idx>>3, c4 = idx&7;
      av[it] = X4[((size_t)(mb*128+r))*128 + kt*8 + c4];
    }
    #pragma unroll
    for (int it=0; it<2; it++){
      int idx = tid + it*256, r = idx>>3, c4 = idx&7;
      bv[it] = W4[((size_t)(nloc+r))*128 + kt*8 + c4];
    }
    __syncthreads();
    unsigned* uA = (unsigned*)sA; unsigned* uB = (unsigned*)sB;
    #pragma unroll
    for (int it=0; it<4; it++){
      int idx = tid + it*256, r = idx>>3, c4 = idx&7;
      unsigned* d = uA + r*36 + c4*4;
      d[0]=tf(av[it].x); d[1]=tf(av[it].y); d[2]=tf(av[it].z); d[3]=tf(av[it].w);
    }
    #pragma unroll
    for (int it=0; it<2; it++){
      int idx = tid + it*256, r = idx>>3, c4 = idx&7;
      unsigned* d = uB + r*36 + c4*4;
      d[0]=tf(bv[it].x); d[1]=tf(bv[it].y); d[2]=tf(bv[it].z); d[3]=tf(bv[it].w);
    }
    __syncthreads();
    #pragma unroll
    for (int ks=0; ks<4; ks++){
      int kb = ks*8;
      unsigned afr[2][4], bfr[4][2];
      #pragma unroll
      for (int wm=0; wm<2; wm++){
        int r = wM*32 + wm*16 + (lane>>2), c = kb + (lane&3);
        afr[wm][0] = uA[r*36 + c];       afr[wm][1] = uA[(r+8)*36 + c];
        afr[wm][2] = uA[r*36 + c + 4];   afr[wm][3] = uA[(r+8)*36 + c + 4];
      }
      #pragma unroll
      for (int wn=0; wn<4; wn++){
        int nr = wN*32 + wn*8 + (lane>>2), c = kb + (lane&3);
        bfr[wn][0] = uB[nr*36 + c]; bfr[wn][1] = uB[nr*36 + c + 4];
      }
      #pragma unroll
      for (int wm=0; wm<2; wm++)
        #pragma unroll
        for (int wn=0; wn<4; wn++) mma8(acc[wm][wn], afr[wm], bfr[wn]);
    }
    __syncthreads();
  }
  #pragma unroll
  for (int wm=0; wm<2; wm++){
    int r0 = mb*128 + wM*32 + wm*16 + (lane>>2);
    #pragma unroll
    for (int wn=0; wn<4; wn++){
      int cl = wN*32 + wn*8 + (lane&3)*2;
      int cg = nb*64 + cl;
      float b0v = bias[nloc + cl], b1v = bias[nloc + cl + 1];
      float2 v0 = make_float2(acc[wm][wn][0]+b0v, acc[wm][wn][1]+b1v);
      float2 v1 = make_float2(acc[wm][wn][2]+b0v, acc[wm][wn][3]+b1v);
      *(float2*)&g_XP[(size_t)r0*NPROJ + cg] = v0;
      *(float2*)&g_XP[(size_t)(r0+8)*NPROJ + cg] = v1;
    }
  }
}

// Persistent bidirectional GRU scan, tensor-core matvec.
// 128 blocks = 2 dirs x 64 col-chunks (8 h-cols, 24 gate rows). 384 threads = 12 warps.
// Warp tile: m16(batch) x n8(gate row) x k8, full K=512 accumulated in C frags.
// smem: sW [24][516] tf32 | sH [512][72] fp32 | sG [64][24]
__global__ void __launch_bounds__(384, 1) k_scan(
    const int* __restrict__ lens,
    const float* __restrict__ whf, const float* __restrict__ whb,
    const float* __restrict__ bhf, const float* __restrict__ bhb,
    float* __restrict__ out){
  extern __shared__ float sm[];
  float* sW = sm;                    // 12384
  float* sH = sm + 24*516;           // 36864
  float* sG = sH + 512*72;           // 1536
  int dir = blockIdx.x & 1, chunk = blockIdx.x >> 1;
  int j0 = chunk*8;
  const float* Wh = dir ? whb : whf;
  const float* bh = dir ? bhb : bhf;
  int tid = threadIdx.x;
  for (int idx = tid; idx < 24*512; idx += 384){
    int r = idx >> 9, k = idx & 511;
    sW[r*516 + k] = __uint_as_float(tf(Wh[(size_t)((r>>3)*512 + j0 + (r&7))*512 + k]));
  }
  for (int idx = tid; idx < 1024; idx += 384){
    int buf = idx >> 9, jl = (idx >> 6) & 7, bb = idx & 63;
    g_ht[buf][dir][j0+jl][bb] = 0.f;
  }
  // mma identities
  int warp = tid >> 5, lane = tid & 31;
  int m0 = (warp & 3)*16, n0 = (warp >> 2)*8;
  int aRow = lane >> 2, aK = lane & 3;
  // update identities (threads 0..255)
  int jl0 = (tid >> 6) & 3, bb0 = tid & 63;
  float b_r0 = bh[j0+jl0],   b_z0 = bh[512+j0+jl0],   b_n0 = bh[1024+j0+jl0];
  float b_r1 = bh[j0+jl0+4], b_z1 = bh[512+j0+jl0+4], b_n1 = bh[1024+j0+jl0+4];
  int L_u = __ldg(&lens[bb0]);
  unsigned sH_base = (unsigned)__cvta_generic_to_shared(sH);
  gbar(dir);
  float hn0 = 0.f, hn1 = 0.f;
  for (int t = 0; t < S; t++){
    int rb = t & 1, wb = 1 - rb;
    bool v = (t < L_u) && (tid < 256);
    int pos = dir ? (L_u-1-t) : t;
    float xr0=0,xz0=0,xn0=0,xr1=0,xz1=0,xn1=0;
    if (v){
      size_t xb = ((size_t)bb0*S + pos)*NPROJ + (size_t)dir*1536 + j0;
      xr0 = __ldg(&g_XP[xb + jl0]);        xr1 = __ldg(&g_XP[xb + jl0 + 4]);
      xz0 = __ldg(&g_XP[xb + 512 + jl0]);  xz1 = __ldg(&g_XP[xb + 512 + jl0 + 4]);
      xn0 = __ldg(&g_XP[xb + 1024 + jl0]); xn1 = __ldg(&g_XP[xb + 1024 + jl0 + 4]);
    }
    // stage h: 4 commit groups of 128 rows x 64 batches (2048 float4 each)
    #pragma unroll
    for (int g = 0; g < 4; g++){
      #pragma unroll
      for (int q = 0; q < 6; q++){
        int idx = q*384 + tid;
        if (idx < 2048){
          int k = g*128 + (idx >> 4), b4 = idx & 15;
          cpasync16(sH_base + (unsigned)(k*72 + b4*4)*4u, &g_ht[rb][dir][k][b4*4]);
        }
      }
      asm volatile("cp.async.commit_group;" ::: "memory");
    }
    float c[4] = {0.f, 0.f, 0.f, 0.f};
    #pragma unroll
    for (int cq = 0; cq < 4; cq++){
      if (cq==0)      asm volatile("cp.async.wait_group 3;" ::: "memory");
      else if (cq==1) asm volatile("cp.async.wait_group 2;" ::: "memory");
      else if (cq==2) asm volatile("cp.async.wait_group 1;" ::: "memory");
      else            asm volatile("cp.async.wait_group 0;" ::: "memory");
      __syncthreads();
      #pragma unroll 4
      for (int i = 0; i < 16; i++){
        int kb = cq*128 + i*8;
        unsigned a[4], b[2];
        a[0] = tf(sH[(kb+aK)*72   + m0 + aRow]);
        a[1] = tf(sH[(kb+aK)*72   + m0 + aRow + 8]);
        a[2] = tf(sH[(kb+aK+4)*72 + m0 + aRow]);
        a[3] = tf(sH[(kb+aK+4)*72 + m0 + aRow + 8]);
        b[0] = __float_as_uint(sW[(n0+aRow)*516 + kb + aK]);
        b[1] = __float_as_uint(sW[(n0+aRow)*516 + kb + aK + 4]);
        mma8(c, a, b);
      }
    }
    // h_old from staged sH
    float hold0 = 0.f, hold1 = 0.f;
    if (tid < 256){
      hold0 = sH[(j0+jl0)*72 + bb0];
      hold1 = sH[(j0+jl0+4)*72 + bb0];
    }
    // write gh frags: C[m][n] -> sG[m*24+n]
    {
      int mA = m0 + (lane>>2), nA = n0 + (lane&3)*2;
      *(float2*)&sG[mA*24 + nA]     = make_float2(c[0], c[1]);
      *(float2*)&sG[(mA+8)*24 + nA] = make_float2(c[2], c[3]);
    }
    __syncthreads();
    hn0 = hold0; hn1 = hold1;
    if (v){
      float gr = sG[bb0*24 + jl0]      + b_r0;
      float gz = sG[bb0*24 + 8 + jl0]  + b_z0;
      float gn = sG[bb0*24 + 16 + jl0] + b_n0;
      float rr = 1.f/(1.f+expf(-(xr0+gr)));
      float zz = 1.f/(1.f+expf(-(xz0+gz)));
      float nn = tanhf(xn0 + rr*gn);
      hn0 = (1.f-zz)*nn + zz*hold0;
      g_ctx[((size_t)bb0*S+pos)*1024 + (size_t)dir*512 + j0 + jl0] = hn0;
      gr = sG[bb0*24 + jl0 + 4]      + b_r1;
      gz = sG[bb0*24 + 8 + jl0 + 4]  + b_z1;
      gn = sG[bb0*24 + 16 + jl0 + 4] + b_n1;
      rr = 1.f/(1.f+expf(-(xr1+gr)));
      zz = 1.f/(1.f+expf(-(xz1+gz)));
      nn = tanhf(xn1 + rr*gn);
      hn1 = (1.f-zz)*nn + zz*hold1;
      g_ctx[((size_t)bb0*S+pos)*1024 + (size_t)dir*512 + j0 + jl0 + 4] = hn1;
    }
    if (tid < 256){
      g_ht[wb][dir][j0+jl0][bb0]   = hn0;
      g_ht[wb][dir][j0+jl0+4][bb0] = hn1;
    }
    gbar(dir);
  }
  if (tid < 256){
    out[POOL + (size_t)dir*B*H + (size_t)bb0*H + j0 + jl0]     = hn0;
    out[POOL + (size_t)dir*B*H + (size_t)bb0*H + j0 + jl0 + 4] = hn1;
  }
}

__global__ void k_segmax(const int* __restrict__ layout, float* __restrict__ out){
  int bs = blockIdx.x;
  int b = bs >> 6, s = bs & 63;
  int lo = layout[b*(NSEG+1) + s], hi = layout[b*(NSEG+1) + s + 1];
  int tid = threadIdx.x;
  #pragma unroll
  for (int q = 0; q < 4; q++){
    int c = tid + q*256;
    float m = -INFINITY;
    for (int t = lo; t < hi; t++)
      m = fmaxf(m, g_ctx[((size_t)b*S + t)*1024 + c]);
    out[(size_t)bs*1024 + c] = m;
  }
}

extern "C" void kernel_launch(void* const* d_in, const int* in_sizes, int n_in,
                              void* d_out, int out_size){
  (void)in_sizes; (void)n_in; (void)out_size;
  const int*   seq    = (const int*)d_in[0];
  const int*   lens   = (const int*)d_in[1];
  const int*   layout = (const int*)d_in[3];
  const float* emb    = (const float*)d_in[4];
  const float* wif    = (const float*)d_in[5];
  const float* whf    = (const float*)d_in[6];
  const float* bif    = (const float*)d_in[7];
  const float* bhf    = (const float*)d_in[8];
  const float* wib    = (const float*)d_in[9];
  const float* whb    = (const float*)d_in[10];
  const float* bib    = (const float*)d_in[11];
  const float* bhb    = (const float*)d_in[12];
  float* out = (float*)d_out;

  k_embed<<<MR*128/256, 256>>>(seq, emb);
  dim3 gg(48, 256);
  k_gemm<<<gg, 256>>>(wif, wib, bif, bib);
  int smem = (24*516 + 512*72 + 1536)*4;
  cudaFuncSetAttribute(k_scan, cudaFuncAttributeMaxDynamicSharedMemorySize, smem);
  k_scan<<<2*NBLKD, 384, smem>>>(lens, whf, whb, bhf, bhb, out);
  k_segmax<<<B*NSEG, 256>>>(layout, out);
}

// round 16
// speedup vs baseline: 3.7660x; 1.1907x over previous
#include <cuda_runtime.h>
#include <cuda_fp16.h>
#include <math.h>

#define B 64
#define S 512
#define H 512
#define E 512
#define NSEG 64
#define MR (B*S)
#define NPROJ 3072
#define POOL (B*NSEG*2*H)
#define NBLKD 64

__device__ __align__(16) float g_X[(size_t)MR*E];
__device__ __align__(16) float g_XP[(size_t)MR*NPROJ];
__device__ __align__(16) float g_ctx[(size_t)MR*2*H];
__device__ __align__(16) __half g_ht16[2][2][B][H];  // [buf][dir][batch][col]
__device__ unsigned long long g_bar2[64];

__device__ __forceinline__ void gbar(int dir){
  __threadfence();
  __syncthreads();
  if (threadIdx.x == 0){
    unsigned long long* p = &g_bar2[dir*32];
    unsigned long long t = atomicAdd(p, 1ULL);
    unsigned long long target = (t/(unsigned long long)NBLKD + 1ULL)*(unsigned long long)NBLKD;
    while (*(volatile unsigned long long*)p < target) __nanosleep(16);
  }
  __syncthreads();
}

__device__ __forceinline__ unsigned tf(float x){
  unsigned u; asm("cvt.rna.tf32.f32 %0, %1;" : "=r"(u) : "f"(x));
  return u;
}
__device__ __forceinline__ void mma8(float c[4], const unsigned a[4], const unsigned b[2]){
  asm volatile("mma.sync.aligned.m16n8k8.row.col.f32.tf32.tf32.f32 "
    "{%0,%1,%2,%3}, {%4,%5,%6,%7}, {%8,%9}, {%0,%1,%2,%3};"
    : "+f"(c[0]), "+f"(c[1]), "+f"(c[2]), "+f"(c[3])
    : "r"(a[0]), "r"(a[1]), "r"(a[2]), "r"(a[3]), "r"(b[0]), "r"(b[1]));
}
__device__ __forceinline__ void mma16(float c[4], const unsigned a[4], const unsigned b[2]){
  asm volatile("mma.sync.aligned.m16n8k16.row.col.f32.f16.f16.f32 "
    "{%0,%1,%2,%3}, {%4,%5,%6,%7}, {%8,%9}, {%0,%1,%2,%3};"
    : "+f"(c[0]), "+f"(c[1]), "+f"(c[2]), "+f"(c[3])
    : "r"(a[0]), "r"(a[1]), "r"(a[2]), "r"(a[3]), "r"(b[0]), "r"(b[1]));
}
__device__ __forceinline__ void cpasync16(unsigned saddr, const void* g){
  asm volatile("cp.async.cg.shared.global [%0], [%1], 16;" :: "r"(saddr), "l"(g) : "memory");
}

__global__ void k_embed(const int* __restrict__ seq, const float* __restrict__ emb){
  size_t i = (size_t)blockIdx.x*256 + threadIdx.x;
  int c = (int)(i & 127); size_t row = i >> 7;
  int tok = seq[row];
  reinterpret_cast<float4*>(g_X)[row*128 + c] =
      reinterpret_cast<const float4*>(emb)[(size_t)tok*128 + c];
}

__global__ void __launch_bounds__(256) k_gemm(
    const float* __restrict__ wf, const float* __restrict__ wb,
    const float* __restrict__ bf, const float* __restrict__ bb){
  __shared__ __align__(16) float sA[128*36];
  __shared__ __align__(16) float sB[64*36];
  int nb = blockIdx.x, mb = blockIdx.y;
  const float* W; const float* bias; int nloc;
  if (nb < 24){ W = wf; bias = bf; nloc = nb*64; }
  else        { W = wb; bias = bb; nloc = (nb-24)*64; }
  int tid = threadIdx.x, lane = tid & 31, warp = tid >> 5;
  int wM = warp & 3, wN = warp >> 2;
  float acc[2][4][4];
  #pragma unroll
  for (int i=0;i<2;i++)
    #pragma unroll
    for (int j=0;j<4;j++)
      #pragma unroll
      for (int k=0;k<4;k++) acc[i][j][k]=0.f;
  const float4* X4 = reinterpret_cast<const float4*>(g_X);
  const float4* W4 = reinterpret_cast<const float4*>(W);
  for (int kt = 0; kt < 16; kt++){
    float4 av[4], bv[2];
    #pragma unroll
    for (int it=0; it<4; it++){
      int idx = tid + it*256, r = idx>>3, c4 = idx&7;
      av[it] = X4[((size_t)(mb*128+r))*128 + kt*8 + c4];
    }
    #pragma unroll
    for (int it=0; it<2; it++){
      int idx = tid + it*256, r = idx>>3, c4 = idx&7;
      bv[it] = W4[((size_t)(nloc+r))*128 + kt*8 + c4];
    }
    __syncthreads();
    unsigned* uA = (unsigned*)sA; unsigned* uB = (unsigned*)sB;
    #pragma unroll
    for (int it=0; it<4; it++){
      int idx = tid + it*256, r = idx>>3, c4 = idx&7;
      unsigned* d = uA + r*36 + c4*4;
      d[0]=tf(av[it].x); d[1]=tf(av[it].y); d[2]=tf(av[it].z); d[3]=tf(av[it].w);
    }
    #pragma unroll
    for (int it=0; it<2; it++){
      int idx = tid + it*256, r = idx>>3, c4 = idx&7;
      unsigned* d = uB + r*36 + c4*4;
      d[0]=tf(bv[it].x); d[1]=tf(bv[it].y); d[2]=tf(bv[it].z); d[3]=tf(bv[it].w);
    }
    __syncthreads();
    #pragma unroll
    for (int ks=0; ks<4; ks++){
      int kb = ks*8;
      unsigned afr[2][4], bfr[4][2];
      #pragma unroll
      for (int wm=0; wm<2; wm++){
        int r = wM*32 + wm*16 + (lane>>2), c = kb + (lane&3);
        afr[wm][0] = uA[r*36 + c];       afr[wm][1] = uA[(r+8)*36 + c];
        afr[wm][2] = uA[r*36 + c + 4];   afr[wm][3] = uA[(r+8)*36 + c + 4];
      }
      #pragma unroll
      for (int wn=0; wn<4; wn++){
        int nr = wN*32 + wn*8 + (lane>>2), c = kb + (lane&3);
        bfr[wn][0] = uB[nr*36 + c]; bfr[wn][1] = uB[nr*36 + c + 4];
      }
      #pragma unroll
      for (int wm=0; wm<2; wm++)
        #pragma unroll
        for (int wn=0; wn<4; wn++) mma8(acc[wm][wn], afr[wm], bfr[wn]);
    }
    __syncthreads();
  }
  #pragma unroll
  for (int wm=0; wm<2; wm++){
    int r0 = mb*128 + wM*32 + wm*16 + (lane>>2);
    #pragma unroll
    for (int wn=0; wn<4; wn++){
      int cl = wN*32 + wn*8 + (lane&3)*2;
      int cg = nb*64 + cl;
      float b0v = bias[nloc + cl], b1v = bias[nloc + cl + 1];
      float2 v0 = make_float2(acc[wm][wn][0]+b0v, acc[wm][wn][1]+b1v);
      float2 v1 = make_float2(acc[wm][wn][2]+b0v, acc[wm][wn][3]+b1v);
      *(float2*)&g_XP[(size_t)r0*NPROJ + cg] = v0;
      *(float2*)&g_XP[(size_t)(r0+8)*NPROJ + cg] = v1;
    }
  }
}

// Persistent bidirectional GRU scan. fp16 h exchange + m16n8k16 fp16 mma + ldmatrix.
// 128 blocks = 2 dirs x 64 col-chunks (8 h-cols, 24 gate rows). 384 threads = 12 warps.
// warp (w&3) = m-tile (16 batches), (w>>2) = n-tile (8 gate rows), full K=512 in C frags.
// smem: sW16 [24][520] | sH16 [64][520] | sG [64][26]
__global__ void __launch_bounds__(384, 1) k_scan(
    const int* __restrict__ lens,
    const float* __restrict__ whf, const float* __restrict__ whb,
    const float* __restrict__ bhf, const float* __restrict__ bhb,
    float* __restrict__ out){
  extern __shared__ __align__(16) char smraw[];
  __half* sW16 = (__half*)smraw;          // 24*520
  __half* sH16 = sW16 + 24*520;           // 64*520
  float*  sG   = (float*)(sH16 + 64*520); // 64*26
  int dir = blockIdx.x & 1, chunk = blockIdx.x >> 1;
  int j0 = chunk*8;
  const float* Wh = dir ? whb : whf;
  const float* bh = dir ? bhb : bhf;
  int tid = threadIdx.x;
  for (int idx = tid; idx < 24*512; idx += 384){
    int r = idx >> 9, k = idx & 511;
    sW16[r*520 + k] = __float2half(Wh[(size_t)((r>>3)*512 + j0 + (r&7))*512 + k]);
  }
  for (int idx = tid; idx < 1024; idx += 384){
    int buf = idx >> 9, jl = (idx >> 6) & 7, bb = idx & 63;
    g_ht16[buf][dir][bb][j0+jl] = __float2half(0.f);
  }
  int warp = tid >> 5, lane = tid & 31;
  int m0 = (warp & 3)*16, n0 = (warp >> 2)*8;
  // ldmatrix lane address: row m0 + (lane&7) + ((lane>>3)&1)*8, col (lane>>4)*8
  int arow = m0 + (lane & 7) + ((lane >> 3) & 1)*8;
  int acol = (lane >> 4)*8;
  unsigned sH_base = (unsigned)__cvta_generic_to_shared(sH16);
  unsigned aaddr0 = sH_base + (unsigned)(arow*520 + acol)*2u;
  const __half* bptr = &sW16[(n0 + (lane>>2))*520 + (lane&3)*2];
  // update identity (threads 0..255)
  int jl0 = (tid >> 6) & 3, bb0 = tid & 63;
  float b_r0 = bh[j0+jl0],   b_z0 = bh[512+j0+jl0],   b_n0 = bh[1024+j0+jl0];
  float b_r1 = bh[j0+jl0+4], b_z1 = bh[512+j0+jl0+4], b_n1 = bh[1024+j0+jl0+4];
  int L_u = __ldg(&lens[bb0]);
  gbar(dir);
  float hold0 = 0.f, hold1 = 0.f;
  for (int t = 0; t < S; t++){
    int rb = t & 1, wb = 1 - rb;
    bool v = (t < L_u) && (tid < 256);
    int pos = dir ? (L_u-1-t) : t;
    float xr0=0,xz0=0,xn0=0,xr1=0,xz1=0,xn1=0;
    if (v){
      size_t xb = ((size_t)bb0*S + pos)*NPROJ + (size_t)dir*1536 + j0;
      xr0 = __ldg(&g_XP[xb + jl0]);        xr1 = __ldg(&g_XP[xb + jl0 + 4]);
      xz0 = __ldg(&g_XP[xb + 512 + jl0]);  xz1 = __ldg(&g_XP[xb + 512 + jl0 + 4]);
      xn0 = __ldg(&g_XP[xb + 1024 + jl0]); xn1 = __ldg(&g_XP[xb + 1024 + jl0 + 4]);
    }
    // stage h: 64 rows x 512 fp16 = 4096 x 16B
    #pragma unroll
    for (int q = 0; q < 11; q++){
      int idx = q*384 + tid;
      if (idx < 4096){
        int b = idx >> 6, u = idx & 63;
        cpasync16(sH_base + (unsigned)(b*520 + u*8)*2u, &g_ht16[rb][dir][b][u*8]);
      }
    }
    asm volatile("cp.async.commit_group;" ::: "memory");
    asm volatile("cp.async.wait_group 0;" ::: "memory");
    __syncthreads();
    float c[4] = {0.f, 0.f, 0.f, 0.f};
    #pragma unroll 8
    for (int i = 0; i < 32; i++){
      unsigned a0,a1,a2,a3;
      asm volatile("ldmatrix.sync.aligned.m8n8.x4.shared.b16 {%0,%1,%2,%3}, [%4];"
        : "=r"(a0), "=r"(a1), "=r"(a2), "=r"(a3)
        : "r"(aaddr0 + (unsigned)i*32u));
      unsigned bf0 = *(const unsigned*)(bptr + i*16);
      unsigned bf1 = *(const unsigned*)(bptr + i*16 + 8);
      unsigned a[4] = {a0,a1,a2,a3};
      unsigned bb2[2] = {bf0,bf1};
      mma16(c, a, bb2);
    }
    {
      int mA = m0 + (lane>>2), nA = n0 + (lane&3)*2;
      *(float2*)&sG[mA*26 + nA]     = make_float2(c[0], c[1]);
      *(float2*)&sG[(mA+8)*26 + nA] = make_float2(c[2], c[3]);
    }
    __syncthreads();
    float hn0 = hold0, hn1 = hold1;
    if (v){
      float gr = sG[bb0*26 + jl0]      + b_r0;
      float gz = sG[bb0*26 + 8 + jl0]  + b_z0;
      float gn = sG[bb0*26 + 16 + jl0] + b_n0;
      float rr = 1.f/(1.f+expf(-(xr0+gr)));
      float zz = 1.f/(1.f+expf(-(xz0+gz)));
      float nn = tanhf(xn0 + rr*gn);
      hn0 = (1.f-zz)*nn + zz*hold0;
      g_ctx[((size_t)bb0*S+pos)*1024 + (size_t)dir*512 + j0 + jl0] = hn0;
      gr = sG[bb0*26 + jl0 + 4]      + b_r1;
      gz = sG[bb0*26 + 8 + jl0 + 4]  + b_z1;
      gn = sG[bb0*26 + 16 + jl0 + 4] + b_n1;
      rr = 1.f/(1.f+expf(-(xr1+gr)));
      zz = 1.f/(1.f+expf(-(xz1+gz)));
      nn = tanhf(xn1 + rr*gn);
      hn1 = (1.f-zz)*nn + zz*hold1;
      g_ctx[((size_t)bb0*S+pos)*1024 + (size_t)dir*512 + j0 + jl0 + 4] = hn1;
    }
    hold0 = hn0; hold1 = hn1;
    if (tid < 256){
      g_ht16[wb][dir][bb0][j0+jl0]   = __float2half(hn0);
      g_ht16[wb][dir][bb0][j0+jl0+4] = __float2half(hn1);
    }
    gbar(dir);
  }
  if (tid < 256){
    out[POOL + (size_t)dir*B*H + (size_t)bb0*H + j0 + jl0]     = hold0;
    out[POOL + (size_t)dir*B*H + (size_t)bb0*H + j0 + jl0 + 4] = hold1;
  }
}

__global__ void k_segmax(const int* __restrict__ layout, float* __restrict__ out){
  int bs = blockIdx.x;
  int b = bs >> 6, s = bs & 63;
  int lo = layout[b*(NSEG+1) + s], hi = layout[b*(NSEG+1) + s + 1];
  int tid = threadIdx.x;
  #pragma unroll
  for (int q = 0; q < 4; q++){
    int c = tid + q*256;
    float m = -INFINITY;
    for (int t = lo; t < hi; t++)
      m = fmaxf(m, g_ctx[((size_t)b*S + t)*1024 + c]);
    out[(size_t)bs*1024 + c] = m;
  }
}

extern "C" void kernel_launch(void* const* d_in, const int* in_sizes, int n_in,
                              void* d_out, int out_size){
  (void)in_sizes; (void)n_in; (void)out_size;
  const int*   seq    = (const int*)d_in[0];
  const int*   lens   = (const int*)d_in[1];
  const int*   layout = (const int*)d_in[3];
  const float* emb    = (const float*)d_in[4];
  const float* wif    = (const float*)d_in[5];
  const float* whf    = (const float*)d_in[6];
  const float* bif    = (const float*)d_in[7];
  const float* bhf    = (const float*)d_in[8];
  const float* wib    = (const float*)d_in[9];
  const float* whb    = (const float*)d_in[10];
  const float* bib    = (const float*)d_in[11];
  const float* bhb    = (const float*)d_in[12];
  float* out = (float*)d_out;

  k_embed<<<MR*128/256, 256>>>(seq, emb);
  dim3 gg(48, 256);
  k_gemm<<<gg, 256>>>(wif, wib, bif, bib);
  int smem = (24*520 + 64*520)*2 + 64*26*4;
  cudaFuncSetAttribute(k_scan, cudaFuncAttributeMaxDynamicSharedMemorySize, smem);
  k_scan<<<2*NBLKD, 384, smem>>>(lens, whf, whb, bhf, bhb, out);
  k_segmax<<<B*NSEG, 256>>>(layout, out);
}